// round 9
// baseline (speedup 1.0000x reference)
#include <cuda_runtime.h>

#define NN 512   // nodes
#define NE 512   // edges
#define D  128   // emb dim
#define H  256   // hidden
#define NI 8192  // incidences

// ---------------- scratch (no allocations allowed) ----------------
__device__ float g_eSum[NE * D];
__device__ float g_eCnt[NE];
__device__ float g_hX [NN * H];
__device__ float g_hEb[NE * H];
__device__ __align__(16) int g_ready[16];   // per-32-row hEb block: 4 jobs each
__device__ int   g_mode;   // 1 = indices are int64, 0 = int32

typedef unsigned long long ull;

// fused triad on packed f32x2: acc += relu(x + e) * w
__device__ __forceinline__ void triad(ull& acc, ull x, ull e, ull w) {
    asm("{\n\t"
        ".reg .f32 lo, hi;\n\t"
        ".reg .b64 t;\n\t"
        "add.rn.f32x2 t, %1, %2;\n\t"
        "mov.b64 {lo, hi}, t;\n\t"
        "max.f32 lo, lo, 0f00000000;\n\t"
        "max.f32 hi, hi, 0f00000000;\n\t"
        "mov.b64 t, {lo, hi};\n\t"
        "fma.rn.f32x2 %0, t, %3, %0;\n\t"
        "}"
        : "+l"(acc) : "l"(x), "l"(e), "l"(w));
}
__device__ __forceinline__ float hsum2(ull t) {
    float lo, hi;
    asm("mov.b64 {%0, %1}, %2;" : "=f"(lo), "=f"(hi) : "l"(t));
    return lo + hi;
}

// ---------------- K0: zero scratch + detect index dtype ----------------
__global__ void k_zero_detect(const void* __restrict__ Ep) {
    int i = blockIdx.x * 256 + threadIdx.x;          // 65*256 covers 16520 float4
    float4 z = make_float4(0.f, 0.f, 0.f, 0.f);
    if (i < 16384) {
        ((float4*)g_eSum)[i] = z;
    } else if (i < 16512) {
        ((float4*)g_eCnt)[i - 16384] = z;
    } else if (i < 16516) {
        int4 zi = make_int4(0, 0, 0, 0);
        ((int4*)g_ready)[i - 16512] = zi;
    }
    if (blockIdx.x == 0 && threadIdx.x == 0) {
        const long long* e64 = (const long long*)Ep;
        int ok = 1;
        #pragma unroll 1
        for (int k = 0; k < 32; k++) {
            long long v = e64[k];
            if (v < 0 || v >= (long long)NE) { ok = 0; break; }
        }
        g_mode = ok;
    }
}

// ---------------- K1: scatter (bids 0..1023) + hX GEMM (bids 1024..1087) ----------
__global__ void __launch_bounds__(256) k_scatter_gemmx(const float* __restrict__ X,
                                                       const void* __restrict__ Vp,
                                                       const void* __restrict__ Ep,
                                                       const float* __restrict__ W1) {
    __shared__ float sm[32 * 36 + 32 * 68];
    int tid = threadIdx.x;
    int bid = blockIdx.x;

    if (bid < 1024) {
        // ----- scatter-sum + counts (vector RED), one warp per incidence -----
        int gid = bid * 256 + tid;                   // NI*32 threads
        int inc = gid >> 5;
        int q   = gid & 31;
        int v, e;
        if (g_mode) {
            v = (int)((const long long*)Vp)[inc];
            e = (int)((const long long*)Ep)[inc];
        } else {
            v = ((const int*)Vp)[inc];
            e = ((const int*)Ep)[inc];
        }
        float4 f = *(const float4*)(X + v * D + q * 4);
        float* dst = g_eSum + e * D + q * 4;
        asm volatile("red.global.add.v4.f32 [%0], {%1, %2, %3, %4};"
                     :: "l"(dst), "f"(f.x), "f"(f.y), "f"(f.z), "f"(f.w) : "memory");
        if (q == 0)
            asm volatile("red.global.add.f32 [%0], %1;"
                         :: "l"(&g_eCnt[e]), "f"(1.0f) : "memory");
        return;
    }

    // ----- hX GEMM: g_hX = X @ W1[:, :128].T ; job tile 32 rows x 64 h -----
    int job = bid - 1024;                            // 0..63
    int r0 = (job >> 2) * 32;
    int h0 = (job & 3) * 64;
    float* sA = sm;                                  // 32*36 [k][row]
    float* sB = sm + 32 * 36;                        // 32*68 [k][h]
    int tx = tid & 15, ty = tid >> 4;

    float acc[2][4];
    #pragma unroll
    for (int i = 0; i < 2; i++)
        #pragma unroll
        for (int j = 0; j < 4; j++) acc[i][j] = 0.0f;

    for (int k0 = 0; k0 < D; k0 += 32) {
        __syncthreads();
        {   // A: 32 rows x 32 k = 256 float4
            int kq = tid & 7;
            int r  = tid >> 3;
            float4 f = *(const float4*)(X + (r0 + r) * D + k0 + kq * 4);
            sA[(kq * 4 + 0) * 36 + r] = f.x;
            sA[(kq * 4 + 1) * 36 + r] = f.y;
            sA[(kq * 4 + 2) * 36 + r] = f.z;
            sA[(kq * 4 + 3) * 36 + r] = f.w;
        }
        #pragma unroll
        for (int i = 0; i < 2; i++) {  // B: 64 h x 32 k = 512 float4
            int lin = tid + 256 * i;
            int kq = lin & 7;
            int hr = lin >> 3;
            float4 g = *(const float4*)(W1 + (h0 + hr) * (2 * D) + k0 + kq * 4);
            sB[(kq * 4 + 0) * 68 + hr] = g.x;
            sB[(kq * 4 + 1) * 68 + hr] = g.y;
            sB[(kq * 4 + 2) * 68 + hr] = g.z;
            sB[(kq * 4 + 3) * 68 + hr] = g.w;
        }
        __syncthreads();

        #pragma unroll
        for (int kk = 0; kk < 32; kk++) {
            float2 a2 = *(float2*)&sA[kk * 36 + 2 * ty];
            float4 b4 = *(float4*)&sB[kk * 68 + 4 * tx];
            #pragma unroll
            for (int i = 0; i < 2; i++) {
                float a = i ? a2.y : a2.x;
                acc[i][0] = fmaf(a, b4.x, acc[i][0]);
                acc[i][1] = fmaf(a, b4.y, acc[i][1]);
                acc[i][2] = fmaf(a, b4.z, acc[i][2]);
                acc[i][3] = fmaf(a, b4.w, acc[i][3]);
            }
        }
    }

    #pragma unroll
    for (int i = 0; i < 2; i++) {
        int gr = r0 + 2 * ty + i;
        #pragma unroll
        for (int j = 0; j < 4; j++)
            g_hX[gr * H + h0 + 4 * tx + j] = acc[i][j];
    }
}

// ---------------- K2: hEb GEMM prologue (64 CTAs) + fused epilogue ----------------
// Epi: out[n,m] = clip(sigmoid( sum_h relu(hX[n,h]+hEb[m,h]) * W2[h] + b2 ))
// CTA tile 16n x 32m, 128 threads, thread tile 2n x 2m, full h (4 chunks of 64).
// Grid (16, 32) = 512 CTAs; first 64 (linear) also compute one hEb job each.
// All 512 CTAs are co-resident (regs/smem allow >=5 CTAs/SM), so spinning on
// g_ready is deadlock-free.
__global__ void __launch_bounds__(128) k_epi(const float* __restrict__ W1,
                                             const float* __restrict__ b1,
                                             const float* __restrict__ W2,
                                             const float* __restrict__ b2,
                                             float* __restrict__ out) {
    __shared__ float sm[32 * 36 + 32 * 68];   // gemm: sA|sB ; epi: sX|sE
    __shared__ float sW[64];
    int tid = threadIdx.x;
    int bix = blockIdx.x;                     // m-block 0..15
    int lbid = blockIdx.y * gridDim.x + bix;  // linear bid

    // ===== prologue: hEb GEMM job (first 64 linear CTAs) =====
    if (lbid < 64) {
        int r0 = (lbid >> 2) * 32;            // hEb rows r0..r0+31 (m-block lbid>>2)
        int h0 = (lbid & 3) * 64;
        float* sA = sm;                       // 32*36 [k][row]
        float* sB = sm + 32 * 36;             // 32*68 [k][h]
        int gtx = tid & 15, gty = tid >> 4;   // gty 0..7 -> 4 rows each

        float acc[4][4];
        #pragma unroll
        for (int i = 0; i < 4; i++)
            #pragma unroll
            for (int j = 0; j < 4; j++) acc[i][j] = 0.0f;

        for (int k0 = 0; k0 < D; k0 += 32) {
            __syncthreads();
            #pragma unroll
            for (int i = 0; i < 2; i++) {     // A: 256 float4, 2 per thread
                int lin = tid + 128 * i;
                int kq = lin & 7;
                int r  = lin >> 3;            // 0..31
                float4 f = *(const float4*)(g_eSum + (r0 + r) * D + k0 + kq * 4);
                float c = g_eCnt[r0 + r];
                float s = 1.0f / fmaxf(c, 1.0f);
                sA[(kq * 4 + 0) * 36 + r] = f.x * s;
                sA[(kq * 4 + 1) * 36 + r] = f.y * s;
                sA[(kq * 4 + 2) * 36 + r] = f.z * s;
                sA[(kq * 4 + 3) * 36 + r] = f.w * s;
            }
            #pragma unroll
            for (int i = 0; i < 4; i++) {     // B: 512 float4, 4 per thread
                int lin = tid + 128 * i;
                int kq = lin & 7;
                int hr = lin >> 3;            // 0..63
                float4 g = *(const float4*)(W1 + (h0 + hr) * (2 * D) + D + k0 + kq * 4);
                sB[(kq * 4 + 0) * 68 + hr] = g.x;
                sB[(kq * 4 + 1) * 68 + hr] = g.y;
                sB[(kq * 4 + 2) * 68 + hr] = g.z;
                sB[(kq * 4 + 3) * 68 + hr] = g.w;
            }
            __syncthreads();

            #pragma unroll
            for (int kk = 0; kk < 32; kk++) {
                float4 a4 = *(float4*)&sA[kk * 36 + 4 * gty];
                float4 b4 = *(float4*)&sB[kk * 68 + 4 * gtx];
                float a[4] = {a4.x, a4.y, a4.z, a4.w};
                float b[4] = {b4.x, b4.y, b4.z, b4.w};
                #pragma unroll
                for (int i = 0; i < 4; i++)
                    #pragma unroll
                    for (int j = 0; j < 4; j++)
                        acc[i][j] = fmaf(a[i], b[j], acc[i][j]);
            }
        }

        #pragma unroll
        for (int i = 0; i < 4; i++) {
            int gr = r0 + 4 * gty + i;
            #pragma unroll
            for (int j = 0; j < 4; j++) {
                int h = h0 + 4 * gtx + j;
                g_hEb[gr * H + h] = acc[i][j] + b1[h];
            }
        }
        __threadfence();
        __syncthreads();
        if (tid == 0) atomicAdd(&g_ready[lbid >> 2], 1);
    }

    // ===== wait for this tile's hEb m-block (4 jobs) =====
    if (tid == 0) {
        while (*(volatile int*)&g_ready[bix] < 4) __nanosleep(64);
    }
    __syncthreads();

    // ===== epilogue =====
    float* sX = sm;                 // 16*66 [n][h-chunk], ld=66 (conflict-free)
    float* sE = sm + 16 * 66;       // 32*66 [m][h-chunk]
    int tx = tid & 15;              // m = m0 + tx + 16j
    int ty = tid >> 4;              // n = n0 + ty + 8i   (ty 0..7)
    int m0 = bix * 32;
    int n0 = blockIdx.y * 16;

    ull acc[2][2];
    #pragma unroll
    for (int i = 0; i < 2; i++)
        #pragma unroll
        for (int j = 0; j < 2; j++) acc[i][j] = 0ULL;

    int xoff[2], eoff[2];
    #pragma unroll
    for (int i = 0; i < 2; i++) xoff[i] = (ty + 8 * i) * 66;
    #pragma unroll
    for (int j = 0; j < 2; j++) eoff[j] = (tx + 16 * j) * 66;

    float4 pX[2], pE[4], pW;

    #define GLOAD(hc)                                                            \
        do {                                                                     \
            _Pragma("unroll")                                                    \
            for (int i_ = 0; i_ < 2; i_++) {          /* 16 rows x 16 quads */   \
                int lin = tid + 128 * i_;                                        \
                int q = lin & 15, r = lin >> 4;                                  \
                pX[i_] = *(const float4*)(g_hX + (n0 + r) * H + (hc) + 4 * q);   \
            }                                                                    \
            _Pragma("unroll")                                                    \
            for (int i_ = 0; i_ < 4; i_++) {          /* 32 rows x 16 quads */   \
                int lin = tid + 128 * i_;                                        \
                int q = lin & 15, r = lin >> 4;                                  \
                pE[i_] = *(const float4*)(g_hEb + (m0 + r) * H + (hc) + 4 * q);  \
            }                                                                    \
            if (tid < 16) pW = *(const float4*)(W2 + (hc) + 4 * tid);            \
        } while (0)

    #define GSTORE()                                                             \
        do {                                                                     \
            _Pragma("unroll")                                                    \
            for (int i_ = 0; i_ < 2; i_++) {                                     \
                int lin = tid + 128 * i_;                                        \
                int q = lin & 15, r = lin >> 4;                                  \
                *(float2*)&sX[r * 66 + 4 * q]     = make_float2(pX[i_].x, pX[i_].y); \
                *(float2*)&sX[r * 66 + 4 * q + 2] = make_float2(pX[i_].z, pX[i_].w); \
            }                                                                    \
            _Pragma("unroll")                                                    \
            for (int i_ = 0; i_ < 4; i_++) {                                     \
                int lin = tid + 128 * i_;                                        \
                int q = lin & 15, r = lin >> 4;                                  \
                *(float2*)&sE[r * 66 + 4 * q]     = make_float2(pE[i_].x, pE[i_].y); \
                *(float2*)&sE[r * 66 + 4 * q + 2] = make_float2(pE[i_].z, pE[i_].w); \
            }                                                                    \
            if (tid < 16) *(float4*)&sW[4 * tid] = pW;                           \
        } while (0)

    ulonglong2 Wb[2];
    ull Xb[2][2][2], Eb[2][2][2];
    #define LOADI(s, h)                                                          \
        do {                                                                     \
            Wb[s] = *(const ulonglong2*)&sW[(h)];                                \
            _Pragma("unroll")                                                    \
            for (int i_ = 0; i_ < 2; i_++) {                                     \
                Xb[s][i_][0] = *(const ull*)&sX[xoff[i_] + (h)];                 \
                Xb[s][i_][1] = *(const ull*)&sX[xoff[i_] + (h) + 2];             \
            }                                                                    \
            _Pragma("unroll")                                                    \
            for (int j_ = 0; j_ < 2; j_++) {                                     \
                Eb[s][j_][0] = *(const ull*)&sE[eoff[j_] + (h)];                 \
                Eb[s][j_][1] = *(const ull*)&sE[eoff[j_] + (h) + 2];             \
            }                                                                    \
        } while (0)
    #define COMP(s)                                                              \
        do {                                                                     \
            _Pragma("unroll")                                                    \
            for (int i_ = 0; i_ < 2; i_++)                                       \
                _Pragma("unroll")                                                \
                for (int j_ = 0; j_ < 2; j_++) {                                 \
                    triad(acc[i_][j_], Xb[s][i_][0], Eb[s][j_][0], Wb[s].x);     \
                    triad(acc[i_][j_], Xb[s][i_][1], Eb[s][j_][1], Wb[s].y);     \
                }                                                                \
        } while (0)

    GLOAD(0);
    GSTORE();
    __syncthreads();

    #pragma unroll 1
    for (int c = 0; c < 4; c++) {
        if (c < 3) GLOAD(64 * (c + 1));       // prefetch next chunk
        LOADI(0, 0);
        #pragma unroll
        for (int it = 0; it < 16; it++) {
            if (it < 15) {
                if (it & 1) LOADI(0, 4 * (it + 1));
                else        LOADI(1, 4 * (it + 1));
            }
            if (it & 1) COMP(1);
            else        COMP(0);
        }
        if (c < 3) {
            __syncthreads();
            GSTORE();
            __syncthreads();
        }
    }
    #undef GLOAD
    #undef GSTORE
    #undef LOADI
    #undef COMP

    // direct sigmoid + clip + store
    float b2v = b2[0];
    #pragma unroll
    for (int i = 0; i < 2; i++) {
        int n = n0 + ty + 8 * i;
        #pragma unroll
        for (int j = 0; j < 2; j++) {
            int m = m0 + tx + 16 * j;
            float lg = hsum2(acc[i][j]) + b2v;
            float p = 1.0f / (1.0f + __expf(-lg));
            p = fminf(fmaxf(p, 1e-6f), 1.0f - 1e-6f);
            out[n * NE + m] = p;
        }
    }
}

// ---------------- launch ----------------
extern "C" void kernel_launch(void* const* d_in, const int* in_sizes, int n_in,
                              void* d_out, int out_size) {
    const float* X  = (const float*)d_in[0];
    const void*  V  = d_in[1];
    const void*  E  = d_in[2];
    const float* W1 = (const float*)d_in[3];
    const float* b1 = (const float*)d_in[4];
    const float* W2 = (const float*)d_in[5];
    const float* b2 = (const float*)d_in[6];
    float* out = (float*)d_out;

    k_zero_detect<<<65, 256>>>(E);                         // zero + detect
    k_scatter_gemmx<<<1088, 256>>>(X, V, E, W1);           // scatter + hX gemm
    k_epi<<<dim3(16, 32), 128>>>(W1, b1, W2, b2, out);     // hEb gemm + epi
}

// round 10
// speedup vs baseline: 1.2002x; 1.2002x over previous
#include <cuda_runtime.h>

#define NN 512   // nodes
#define NE 512   // edges
#define D  128   // emb dim
#define H  256   // hidden
#define NI 8192  // incidences

// ---------------- scratch (no allocations allowed) ----------------
__device__ float g_eSum[NE * D];
__device__ float g_eCnt[NE];
__device__ float g_hX [NN * H];
__device__ float g_hEb[NE * H];
__device__ int   g_mode;   // 1 = indices are int64, 0 = int32

typedef unsigned long long ull;

// fused triad on packed f32x2: acc += relu(x + e) * w
__device__ __forceinline__ void triad(ull& acc, ull x, ull e, ull w) {
    asm("{\n\t"
        ".reg .f32 lo, hi;\n\t"
        ".reg .b64 t;\n\t"
        "add.rn.f32x2 t, %1, %2;\n\t"
        "mov.b64 {lo, hi}, t;\n\t"
        "max.f32 lo, lo, 0f00000000;\n\t"
        "max.f32 hi, hi, 0f00000000;\n\t"
        "mov.b64 t, {lo, hi};\n\t"
        "fma.rn.f32x2 %0, t, %3, %0;\n\t"
        "}"
        : "+l"(acc) : "l"(x), "l"(e), "l"(w));
}
__device__ __forceinline__ float hsum2(ull t) {
    float lo, hi;
    asm("mov.b64 {%0, %1}, %2;" : "=f"(lo), "=f"(hi) : "l"(t));
    return lo + hi;
}

// ---------------- K0: zero scratch + warp-parallel dtype detect ----------------
__global__ void k_zero_detect(const void* __restrict__ Ep) {
    int i = blockIdx.x * 256 + threadIdx.x;          // 65*256 covers 16512 float4
    float4 z = make_float4(0.f, 0.f, 0.f, 0.f);
    if (i < 16384) {
        ((float4*)g_eSum)[i] = z;
    } else if (i < 16512) {
        ((float4*)g_eCnt)[i - 16384] = z;
    }
    if (blockIdx.x == 0 && threadIdx.x < 32) {
        // 32 lanes read 32 int64 candidates in parallel; if the buffer is
        // really int32, some lane sees a value outside [0, NE).
        long long v = ((const long long*)Ep)[threadIdx.x];
        unsigned bad = __ballot_sync(0xFFFFFFFFu, v < 0 || v >= (long long)NE);
        if (threadIdx.x == 0) g_mode = (bad == 0u) ? 1 : 0;
    }
}

// ---------------- K1: scatter-sum + counts (vector RED) ----------------
__global__ void k_scatter(const float* __restrict__ X,
                          const void* __restrict__ Vp,
                          const void* __restrict__ Ep) {
    int gid = blockIdx.x * 256 + threadIdx.x;        // NI*32 threads
    int inc = gid >> 5;
    int q   = gid & 31;
    int v, e;
    if (g_mode) {
        v = (int)((const long long*)Vp)[inc];
        e = (int)((const long long*)Ep)[inc];
    } else {
        v = ((const int*)Vp)[inc];
        e = ((const int*)Ep)[inc];
    }
    float4 f = *(const float4*)(X + v * D + q * 4);
    float* dst = g_eSum + e * D + q * 4;
    asm volatile("red.global.add.v4.f32 [%0], {%1, %2, %3, %4};"
                 :: "l"(dst), "f"(f.x), "f"(f.y), "f"(f.z), "f"(f.w) : "memory");
    if (q == 0)
        asm volatile("red.global.add.f32 [%0], %1;"
                     :: "l"(&g_eCnt[e]), "f"(1.0f) : "memory");
}

// ---------------- K2: fused GEMM for hX and hEb ----------------
// Rows 0..511   : A = X,                out g_hX  = X @ W1[:, :128].T
// Rows 512..1023: A = eSum/max(cnt,1),  out g_hEb = eX @ W1[:, 128:].T + b1
__global__ void __launch_bounds__(256) k_gemm(const float* __restrict__ X,
                                              const float* __restrict__ W1,
                                              const float* __restrict__ b1) {
    __shared__ float sA[32 * 36];   // [k][row], ld=36
    __shared__ float sB[32 * 68];   // [k][h],  ld=68
    int tid = threadIdx.x;
    int tx = tid & 15, ty = tid >> 4;
    int h0 = blockIdx.x * 64;
    int r0 = blockIdx.y * 32;
    bool isX = (r0 < NN);
    int koff = isX ? 0 : D;

    float acc[2][4];
    #pragma unroll
    for (int i = 0; i < 2; i++)
        #pragma unroll
        for (int j = 0; j < 4; j++) acc[i][j] = 0.0f;

    for (int k0 = 0; k0 < D; k0 += 32) {
        __syncthreads();
        {   // A: 32 rows x 32 k = 256 float4
            int kq = tid & 7;
            int r  = tid >> 3;
            int gr = r0 + r;
            float4 f;
            if (isX) {
                f = *(const float4*)(X + gr * D + k0 + kq * 4);
            } else {
                f = *(const float4*)(g_eSum + (gr - NN) * D + k0 + kq * 4);
                float c = g_eCnt[gr - NN];
                float s = 1.0f / fmaxf(c, 1.0f);
                f.x *= s; f.y *= s; f.z *= s; f.w *= s;
            }
            sA[(kq * 4 + 0) * 36 + r] = f.x;
            sA[(kq * 4 + 1) * 36 + r] = f.y;
            sA[(kq * 4 + 2) * 36 + r] = f.z;
            sA[(kq * 4 + 3) * 36 + r] = f.w;
        }
        #pragma unroll
        for (int i = 0; i < 2; i++) {  // B: 64 h x 32 k = 512 float4
            int lin = tid + 256 * i;
            int kq = lin & 7;
            int hr = lin >> 3;
            float4 g = *(const float4*)(W1 + (h0 + hr) * (2 * D) + koff + k0 + kq * 4);
            sB[(kq * 4 + 0) * 68 + hr] = g.x;
            sB[(kq * 4 + 1) * 68 + hr] = g.y;
            sB[(kq * 4 + 2) * 68 + hr] = g.z;
            sB[(kq * 4 + 3) * 68 + hr] = g.w;
        }
        __syncthreads();

        #pragma unroll
        for (int kk = 0; kk < 32; kk++) {
            float2 a2 = *(float2*)&sA[kk * 36 + 2 * ty];
            float4 b4 = *(float4*)&sB[kk * 68 + 4 * tx];
            float a[2] = {a2.x, a2.y};
            float b[4] = {b4.x, b4.y, b4.z, b4.w};
            #pragma unroll
            for (int i = 0; i < 2; i++)
                #pragma unroll
                for (int j = 0; j < 4; j++)
                    acc[i][j] = fmaf(a[i], b[j], acc[i][j]);
        }
    }

    #pragma unroll
    for (int i = 0; i < 2; i++) {
        int gr = r0 + 2 * ty + i;
        #pragma unroll
        for (int j = 0; j < 4; j++) {
            int h = h0 + 4 * tx + j;
            if (isX) g_hX[gr * H + h] = acc[i][j];
            else     g_hEb[(gr - NN) * H + h] = acc[i][j] + b1[h];
        }
    }
}

// ---------------- K3: fused relu-dot + sigmoid epilogue ----------------
// out[n,m] = clip(sigmoid( sum_h relu(hX[n,h]+hEb[m,h]) * W2[h] + b2 ))
// CTA tile 16n x 32m, 128 threads (4 warps), thread tile 2n x 2m, full h in
// 4 chunks of 64. Grid (16, 32) = 512 CTAs. smem ld=66: conflict-free LDS.64
// for both the spread (tx) and near-broadcast (ty) operands.
__global__ void __launch_bounds__(128) k_epi(const float* __restrict__ W2,
                                             const float* __restrict__ b2,
                                             float* __restrict__ out) {
    __shared__ float sX[16 * 66];   // [n][h-chunk], ld=66
    __shared__ float sE[32 * 66];   // [m][h-chunk], ld=66
    __shared__ float sW[64];
    int tid = threadIdx.x;
    int tx = tid & 15;              // m = m0 + tx + 16j
    int ty = tid >> 4;              // n = n0 + ty + 8i   (ty 0..7)
    int m0 = blockIdx.x * 32;
    int n0 = blockIdx.y * 16;

    ull acc[2][2];
    #pragma unroll
    for (int i = 0; i < 2; i++)
        #pragma unroll
        for (int j = 0; j < 2; j++) acc[i][j] = 0ULL;

    int xoff[2], eoff[2];
    #pragma unroll
    for (int i = 0; i < 2; i++) xoff[i] = (ty + 8 * i) * 66;
    #pragma unroll
    for (int j = 0; j < 2; j++) eoff[j] = (tx + 16 * j) * 66;

    float4 pX[2], pE[4], pW;

    // gmem prefetch of chunk hc into registers
    #define GLOAD(hc)                                                            \
        do {                                                                     \
            _Pragma("unroll")                                                    \
            for (int i_ = 0; i_ < 2; i_++) {          /* 16 rows x 16 quads */   \
                int lin = tid + 128 * i_;                                        \
                int q = lin & 15, r = lin >> 4;                                  \
                pX[i_] = *(const float4*)(g_hX + (n0 + r) * H + (hc) + 4 * q);   \
            }                                                                    \
            _Pragma("unroll")                                                    \
            for (int i_ = 0; i_ < 4; i_++) {          /* 32 rows x 16 quads */   \
                int lin = tid + 128 * i_;                                        \
                int q = lin & 15, r = lin >> 4;                                  \
                pE[i_] = *(const float4*)(g_hEb + (m0 + r) * H + (hc) + 4 * q);  \
            }                                                                    \
            if (tid < 16) pW = *(const float4*)(W2 + (hc) + 4 * tid);            \
        } while (0)

    #define GSTORE()                                                             \
        do {                                                                     \
            _Pragma("unroll")                                                    \
            for (int i_ = 0; i_ < 2; i_++) {                                     \
                int lin = tid + 128 * i_;                                        \
                int q = lin & 15, r = lin >> 4;                                  \
                *(float2*)&sX[r * 66 + 4 * q]     = make_float2(pX[i_].x, pX[i_].y); \
                *(float2*)&sX[r * 66 + 4 * q + 2] = make_float2(pX[i_].z, pX[i_].w); \
            }                                                                    \
            _Pragma("unroll")                                                    \
            for (int i_ = 0; i_ < 4; i_++) {                                     \
                int lin = tid + 128 * i_;                                        \
                int q = lin & 15, r = lin >> 4;                                  \
                *(float2*)&sE[r * 66 + 4 * q]     = make_float2(pE[i_].x, pE[i_].y); \
                *(float2*)&sE[r * 66 + 4 * q + 2] = make_float2(pE[i_].z, pE[i_].w); \
            }                                                                    \
            if (tid < 16) *(float4*)&sW[4 * tid] = pW;                           \
        } while (0)

    ulonglong2 Wb[2];
    ull Xb[2][2][2], Eb[2][2][2];
    #define LOADI(s, h)                                                          \
        do {                                                                     \
            Wb[s] = *(const ulonglong2*)&sW[(h)];                                \
            _Pragma("unroll")                                                    \
            for (int i_ = 0; i_ < 2; i_++) {                                     \
                Xb[s][i_][0] = *(const ull*)&sX[xoff[i_] + (h)];                 \
                Xb[s][i_][1] = *(const ull*)&sX[xoff[i_] + (h) + 2];             \
            }                                                                    \
            _Pragma("unroll")                                                    \
            for (int j_ = 0; j_ < 2; j_++) {                                     \
                Eb[s][j_][0] = *(const ull*)&sE[eoff[j_] + (h)];                 \
                Eb[s][j_][1] = *(const ull*)&sE[eoff[j_] + (h) + 2];             \
            }                                                                    \
        } while (0)
    #define COMP(s)                                                              \
        do {                                                                     \
            _Pragma("unroll")                                                    \
            for (int i_ = 0; i_ < 2; i_++)                                       \
                _Pragma("unroll")                                                \
                for (int j_ = 0; j_ < 2; j_++) {                                 \
                    triad(acc[i_][j_], Xb[s][i_][0], Eb[s][j_][0], Wb[s].x);     \
                    triad(acc[i_][j_], Xb[s][i_][1], Eb[s][j_][1], Wb[s].y);     \
                }                                                                \
        } while (0)

    GLOAD(0);
    GSTORE();
    __syncthreads();

    #pragma unroll 1
    for (int c = 0; c < 4; c++) {
        if (c < 3) GLOAD(64 * (c + 1));       // prefetch next chunk
        LOADI(0, 0);
        #pragma unroll
        for (int it = 0; it < 16; it++) {
            if (it < 15) {
                if (it & 1) LOADI(0, 4 * (it + 1));
                else        LOADI(1, 4 * (it + 1));
            }
            if (it & 1) COMP(1);
            else        COMP(0);
        }
        if (c < 3) {
            __syncthreads();
            GSTORE();
            __syncthreads();
        }
    }
    #undef GLOAD
    #undef GSTORE
    #undef LOADI
    #undef COMP

    // direct sigmoid + clip + store (coalesced 64B segments)
    float b2v = b2[0];
    #pragma unroll
    for (int i = 0; i < 2; i++) {
        int n = n0 + ty + 8 * i;
        #pragma unroll
        for (int j = 0; j < 2; j++) {
            int m = m0 + tx + 16 * j;
            float lg = hsum2(acc[i][j]) + b2v;
            float p = 1.0f / (1.0f + __expf(-lg));
            p = fminf(fmaxf(p, 1e-6f), 1.0f - 1e-6f);
            out[n * NE + m] = p;
        }
    }
}

// ---------------- launch ----------------
extern "C" void kernel_launch(void* const* d_in, const int* in_sizes, int n_in,
                              void* d_out, int out_size) {
    const float* X  = (const float*)d_in[0];
    const void*  V  = d_in[1];
    const void*  E  = d_in[2];
    const float* W1 = (const float*)d_in[3];
    const float* b1 = (const float*)d_in[4];
    const float* W2 = (const float*)d_in[5];
    const float* b2 = (const float*)d_in[6];
    float* out = (float*)d_out;

    k_zero_detect<<<65, 256>>>(E);                             // zero + fast detect
    k_scatter<<<(NI * 32) / 256, 256>>>(X, V, E);              // 1024 blocks
    k_gemm<<<dim3(H / 64, (NN + NE) / 32), 256>>>(X, W1, b1);  // (4,32) = 128 CTAs
    k_epi<<<dim3(NE / 32, NN / 16), 128>>>(W2, b2, out);       // (16,32) = 512 CTAs
}

// round 11
// speedup vs baseline: 1.3007x; 1.0837x over previous
#include <cuda_runtime.h>

#define NN 512   // nodes
#define NE 512   // edges
#define D  128   // emb dim
#define H  256   // hidden
#define NI 8192  // incidences

// ---------------- scratch (no allocations allowed) ----------------
__device__ float g_eSum[NE * D];
__device__ float g_eCnt[NE];
__device__ float g_hX [NN * H];
__device__ float g_hEb[NE * H];
__device__ int   g_mode;   // 1 = indices are int64, 0 = int32

typedef unsigned long long ull;

// fused triad on packed f32x2: acc += relu(x + e) * w
__device__ __forceinline__ void triad(ull& acc, ull x, ull e, ull w) {
    asm("{\n\t"
        ".reg .f32 lo, hi;\n\t"
        ".reg .b64 t;\n\t"
        "add.rn.f32x2 t, %1, %2;\n\t"
        "mov.b64 {lo, hi}, t;\n\t"
        "max.f32 lo, lo, 0f00000000;\n\t"
        "max.f32 hi, hi, 0f00000000;\n\t"
        "mov.b64 t, {lo, hi};\n\t"
        "fma.rn.f32x2 %0, t, %3, %0;\n\t"
        "}"
        : "+l"(acc) : "l"(x), "l"(e), "l"(w));
}
__device__ __forceinline__ float hsum2(ull t) {
    float lo, hi;
    asm("mov.b64 {%0, %1}, %2;" : "=f"(lo), "=f"(hi) : "l"(t));
    return lo + hi;
}

// ---------------- K0: zero scratch + warp-parallel dtype detect ----------------
__global__ void k_zero_detect(const void* __restrict__ Ep) {
    int i = blockIdx.x * 256 + threadIdx.x;          // 65*256 covers 16512 float4
    float4 z = make_float4(0.f, 0.f, 0.f, 0.f);
    if (i < 16384) {
        ((float4*)g_eSum)[i] = z;
    } else if (i < 16512) {
        ((float4*)g_eCnt)[i - 16384] = z;
    }
    if (blockIdx.x == 0 && threadIdx.x < 32) {
        long long v = ((const long long*)Ep)[threadIdx.x];
        unsigned bad = __ballot_sync(0xFFFFFFFFu, v < 0 || v >= (long long)NE);
        if (threadIdx.x == 0) g_mode = (bad == 0u) ? 1 : 0;
    }
}

// ---------------- K1: scatter-sum + counts (vector RED) ----------------
__global__ void k_scatter(const float* __restrict__ X,
                          const void* __restrict__ Vp,
                          const void* __restrict__ Ep) {
    int gid = blockIdx.x * 256 + threadIdx.x;        // NI*32 threads
    int inc = gid >> 5;
    int q   = gid & 31;
    int v, e;
    if (g_mode) {
        v = (int)((const long long*)Vp)[inc];
        e = (int)((const long long*)Ep)[inc];
    } else {
        v = ((const int*)Vp)[inc];
        e = ((const int*)Ep)[inc];
    }
    float4 f = *(const float4*)(X + v * D + q * 4);
    float* dst = g_eSum + e * D + q * 4;
    asm volatile("red.global.add.v4.f32 [%0], {%1, %2, %3, %4};"
                 :: "l"(dst), "f"(f.x), "f"(f.y), "f"(f.z), "f"(f.w) : "memory");
    if (q == 0)
        asm volatile("red.global.add.f32 [%0], %1;"
                     :: "l"(&g_eCnt[e]), "f"(1.0f) : "memory");
}

// ---------------- K2: fused GEMM for hX and hEb ----------------
__global__ void __launch_bounds__(256) k_gemm(const float* __restrict__ X,
                                              const float* __restrict__ W1,
                                              const float* __restrict__ b1) {
    __shared__ float sA[32 * 36];   // [k][row], ld=36
    __shared__ float sB[32 * 68];   // [k][h],  ld=68
    int tid = threadIdx.x;
    int tx = tid & 15, ty = tid >> 4;
    int h0 = blockIdx.x * 64;
    int r0 = blockIdx.y * 32;
    bool isX = (r0 < NN);
    int koff = isX ? 0 : D;

    float acc[2][4];
    #pragma unroll
    for (int i = 0; i < 2; i++)
        #pragma unroll
        for (int j = 0; j < 4; j++) acc[i][j] = 0.0f;

    for (int k0 = 0; k0 < D; k0 += 32) {
        __syncthreads();
        {   // A: 32 rows x 32 k = 256 float4
            int kq = tid & 7;
            int r  = tid >> 3;
            int gr = r0 + r;
            float4 f;
            if (isX) {
                f = *(const float4*)(X + gr * D + k0 + kq * 4);
            } else {
                f = *(const float4*)(g_eSum + (gr - NN) * D + k0 + kq * 4);
                float c = g_eCnt[gr - NN];
                float s = 1.0f / fmaxf(c, 1.0f);
                f.x *= s; f.y *= s; f.z *= s; f.w *= s;
            }
            sA[(kq * 4 + 0) * 36 + r] = f.x;
            sA[(kq * 4 + 1) * 36 + r] = f.y;
            sA[(kq * 4 + 2) * 36 + r] = f.z;
            sA[(kq * 4 + 3) * 36 + r] = f.w;
        }
        #pragma unroll
        for (int i = 0; i < 2; i++) {  // B: 64 h x 32 k = 512 float4
            int lin = tid + 256 * i;
            int kq = lin & 7;
            int hr = lin >> 3;
            float4 g = *(const float4*)(W1 + (h0 + hr) * (2 * D) + koff + k0 + kq * 4);
            sB[(kq * 4 + 0) * 68 + hr] = g.x;
            sB[(kq * 4 + 1) * 68 + hr] = g.y;
            sB[(kq * 4 + 2) * 68 + hr] = g.z;
            sB[(kq * 4 + 3) * 68 + hr] = g.w;
        }
        __syncthreads();

        #pragma unroll
        for (int kk = 0; kk < 32; kk++) {
            float2 a2 = *(float2*)&sA[kk * 36 + 2 * ty];
            float4 b4 = *(float4*)&sB[kk * 68 + 4 * tx];
            float a[2] = {a2.x, a2.y};
            float b[4] = {b4.x, b4.y, b4.z, b4.w};
            #pragma unroll
            for (int i = 0; i < 2; i++)
                #pragma unroll
                for (int j = 0; j < 4; j++)
                    acc[i][j] = fmaf(a[i], b[j], acc[i][j]);
        }
    }

    #pragma unroll
    for (int i = 0; i < 2; i++) {
        int gr = r0 + 2 * ty + i;
        #pragma unroll
        for (int j = 0; j < 4; j++) {
            int h = h0 + 4 * tx + j;
            if (isX) g_hX[gr * H + h] = acc[i][j];
            else     g_hEb[(gr - NN) * H + h] = acc[i][j] + b1[h];
        }
    }
}

// ---------------- K3: fused relu-dot + sigmoid epilogue ----------------
// out[n,m] = clip(sigmoid( sum_h relu(hX[n,h]+hEb[m,h]) * W2[h] + b2 ))
// CTA tile 16n x 32m, 256 threads in TWO warp-groups: wg0 does h[0,128),
// wg1 does h[128,256), each with private smem buffers and named barriers.
// Thread tile 2n x 2m per warp-group thread; partials combined via smem.
// Grid (16, 32) = 512 CTAs, 8 warps each -> ~3.4 CTAs/SM, occ ~44%.
__global__ void __launch_bounds__(256) k_epi(const float* __restrict__ W2,
                                             const float* __restrict__ b2,
                                             float* __restrict__ out) {
    __shared__ float sX[2][16 * 68];   // [wg][n][h-chunk], ld=68 (16B aligned)
    __shared__ float sE[2][32 * 68];   // [wg][m][h-chunk]
    __shared__ float sW[2][64];
    __shared__ float sRed[512];        // wg1 partials
    int tid = threadIdx.x;
    int wg = tid >> 7;                 // warp-group 0/1
    int wtid = tid & 127;
    int tx = wtid & 15;                // m = m0 + tx + 16j
    int ty = wtid >> 4;                // n = n0 + ty + 8i   (ty 0..7)
    int m0 = blockIdx.x * 32;
    int n0 = blockIdx.y * 16;
    int hbase = wg * 128;              // this wg's h range: [hbase, hbase+128)

    float* sXw = sX[wg];
    float* sEw = sE[wg];
    float* sWw = sW[wg];

    #define WGBAR() asm volatile("bar.sync %0, 128;" :: "r"(wg + 1) : "memory")

    ull acc[2][2];
    #pragma unroll
    for (int i = 0; i < 2; i++)
        #pragma unroll
        for (int j = 0; j < 2; j++) acc[i][j] = 0ULL;

    int xoff[2], eoff[2];
    #pragma unroll
    for (int i = 0; i < 2; i++) xoff[i] = (ty + 8 * i) * 68;
    #pragma unroll
    for (int j = 0; j < 2; j++) eoff[j] = (tx + 16 * j) * 68;

    float4 pX[2], pE[4], pW;

    // gmem prefetch of chunk hc into registers (per warp-group, 128 threads)
    #define GLOAD(hc)                                                            \
        do {                                                                     \
            _Pragma("unroll")                                                    \
            for (int i_ = 0; i_ < 2; i_++) {          /* 16 rows x 16 quads */   \
                int lin = wtid + 128 * i_;                                       \
                int q = lin & 15, r = lin >> 4;                                  \
                pX[i_] = *(const float4*)(g_hX + (n0 + r) * H + (hc) + 4 * q);   \
            }                                                                    \
            _Pragma("unroll")                                                    \
            for (int i_ = 0; i_ < 4; i_++) {          /* 32 rows x 16 quads */   \
                int lin = wtid + 128 * i_;                                       \
                int q = lin & 15, r = lin >> 4;                                  \
                pE[i_] = *(const float4*)(g_hEb + (m0 + r) * H + (hc) + 4 * q);  \
            }                                                                    \
            if (wtid < 16) pW = *(const float4*)(W2 + (hc) + 4 * wtid);          \
        } while (0)

    #define GSTORE()                                                             \
        do {                                                                     \
            _Pragma("unroll")                                                    \
            for (int i_ = 0; i_ < 2; i_++) {                                     \
                int lin = wtid + 128 * i_;                                       \
                int q = lin & 15, r = lin >> 4;                                  \
                *(float4*)&sXw[r * 68 + 4 * q] = pX[i_];                         \
            }                                                                    \
            _Pragma("unroll")                                                    \
            for (int i_ = 0; i_ < 4; i_++) {                                     \
                int lin = wtid + 128 * i_;                                       \
                int q = lin & 15, r = lin >> 4;                                  \
                *(float4*)&sEw[r * 68 + 4 * q] = pE[i_];                         \
            }                                                                    \
            if (wtid < 16) *(float4*)&sWw[4 * wtid] = pW;                        \
        } while (0)

    ulonglong2 Wb[2], Xb[2][2], Eb[2][2];
    #define LOADI(s, h)                                                          \
        do {                                                                     \
            Wb[s] = *(const ulonglong2*)&sWw[(h)];                               \
            _Pragma("unroll")                                                    \
            for (int i_ = 0; i_ < 2; i_++)                                       \
                Xb[s][i_] = *(const ulonglong2*)&sXw[xoff[i_] + (h)];            \
            _Pragma("unroll")                                                    \
            for (int j_ = 0; j_ < 2; j_++)                                       \
                Eb[s][j_] = *(const ulonglong2*)&sEw[eoff[j_] + (h)];            \
        } while (0)
    #define COMP(s)                                                              \
        do {                                                                     \
            _Pragma("unroll")                                                    \
            for (int i_ = 0; i_ < 2; i_++)                                       \
                _Pragma("unroll")                                                \
                for (int j_ = 0; j_ < 2; j_++) {                                 \
                    triad(acc[i_][j_], Xb[s][i_].x, Eb[s][j_].x, Wb[s].x);       \
                    triad(acc[i_][j_], Xb[s][i_].y, Eb[s][j_].y, Wb[s].y);       \
                }                                                                \
        } while (0)

    GLOAD(hbase);
    GSTORE();
    WGBAR();

    #pragma unroll 1
    for (int c = 0; c < 2; c++) {
        if (c == 0) GLOAD(hbase + 64);       // prefetch this wg's next chunk
        LOADI(0, 0);
        #pragma unroll
        for (int it = 0; it < 16; it++) {
            if (it < 15) {
                if (it & 1) LOADI(0, 4 * (it + 1));
                else        LOADI(1, 4 * (it + 1));
            }
            if (it & 1) COMP(1);
            else        COMP(0);
        }
        if (c == 0) {
            WGBAR();
            GSTORE();
            WGBAR();
        }
    }
    #undef GLOAD
    #undef GSTORE
    #undef LOADI
    #undef COMP
    #undef WGBAR

    // combine warp-group partials: wg1 -> smem, wg0 adds + sigmoid + store
    float r0v = hsum2(acc[0][0]);
    float r1v = hsum2(acc[0][1]);
    float r2v = hsum2(acc[1][0]);
    float r3v = hsum2(acc[1][1]);
    if (wg == 1)
        *(float4*)&sRed[wtid * 4] = make_float4(r0v, r1v, r2v, r3v);
    __syncthreads();
    if (wg == 0) {
        float4 o = *(float4*)&sRed[wtid * 4];
        float lg[2][2] = {{r0v + o.x, r1v + o.y}, {r2v + o.z, r3v + o.w}};
        float b2v = b2[0];
        #pragma unroll
        for (int i = 0; i < 2; i++) {
            int n = n0 + ty + 8 * i;
            #pragma unroll
            for (int j = 0; j < 2; j++) {
                int m = m0 + tx + 16 * j;
                float p = 1.0f / (1.0f + __expf(-(lg[i][j] + b2v)));
                p = fminf(fmaxf(p, 1e-6f), 1.0f - 1e-6f);
                out[n * NE + m] = p;
            }
        }
    }
}

// ---------------- launch ----------------
extern "C" void kernel_launch(void* const* d_in, const int* in_sizes, int n_in,
                              void* d_out, int out_size) {
    const float* X  = (const float*)d_in[0];
    const void*  V  = d_in[1];
    const void*  E  = d_in[2];
    const float* W1 = (const float*)d_in[3];
    const float* b1 = (const float*)d_in[4];
    const float* W2 = (const float*)d_in[5];
    const float* b2 = (const float*)d_in[6];
    float* out = (float*)d_out;

    k_zero_detect<<<65, 256>>>(E);                             // zero + fast detect
    k_scatter<<<(NI * 32) / 256, 256>>>(X, V, E);              // 1024 blocks
    k_gemm<<<dim3(H / 64, (NN + NE) / 32), 256>>>(X, W1, b1);  // (4,32) = 128 CTAs
    k_epi<<<dim3(NE / 32, NN / 16), 256>>>(W2, b2, out);       // (16,32) = 512 CTAs
}